// round 3
// baseline (speedup 1.0000x reference)
#include <cuda_runtime.h>
#include <cstdint>

#define NC 10
#define D  64

__device__ float g_cc[NC * D];
__device__ int   g_flag;

__device__ __forceinline__ float sigmoidf_(float x) {
    return 1.0f / (1.0f + __expf(-x));
}

__device__ __forceinline__ void cp_async16(uint32_t smem_addr, const void* gptr) {
    asm volatile("cp.async.cg.shared.global [%0], [%1], 16;\n"
                 :: "r"(smem_addr), "l"(gptr));
}
__device__ __forceinline__ void cp_commit() {
    asm volatile("cp.async.commit_group;\n");
}
template <int N>
__device__ __forceinline__ void cp_wait() {
    asm volatile("cp.async.wait_group %0;\n" :: "n"(N));
}

__global__ void reset_kernel() { g_flag = 0; }

// Shared dynamic smem size for both roles (floats)
#define DYN_FLOATS 19328
#define DYN_BYTES  (DYN_FLOATS * 4)

// ---- core smem layout (floats) ----
#define C_BUF0 0          // 64x68 weight tile
#define C_BUF1 4352
#define C_CC   8704       // 640
#define C_K    9344
#define C_V    9984
#define C_TMP  10624
#define C_Q    11264
#define C_NEW  11904
#define C_GI   12544      // 10 x 192
#define C_GH   14464
#define C_H2   16384      // 10 x 128
#define C_ATTN 17664      // 100
#define C_MEAN 17764      // 10
#define C_RSTD 17776      // 10

// ---- MLP smem layout (floats) ----
#define M_WA 0            // 2 slots x 64 x 68
#define M_WB 8704
#define M_CC 17408        // 640
#define M_H  18048        // 2 x 640

__global__ void __launch_bounds__(128)
fused_kernel(
    const float* __restrict__ cc0,
    const float* __restrict__ Wk, const float* __restrict__ bk,
    const float* __restrict__ Wq, const float* __restrict__ bq,
    const float* __restrict__ Wv, const float* __restrict__ bv,
    const float* __restrict__ cc_g, const float* __restrict__ cc_b,
    const float* __restrict__ W_ih, const float* __restrict__ W_hh,
    const float* __restrict__ b_ih, const float* __restrict__ b_hh,
    const float* __restrict__ ln_g, const float* __restrict__ ln_b,
    const float* __restrict__ W1, const float* __restrict__ b1,
    const float* __restrict__ W2, const float* __restrict__ b2,
    const float* __restrict__ Wa, const float* __restrict__ ba,
    const float* __restrict__ Wb, const float* __restrict__ bb,
    float* __restrict__ out)
{
    extern __shared__ float dyn[];
    const int tid = threadIdx.x;

    if (blockIdx.x == 0) {
        // =================== CORE: slot-attention iterations ===================
        float* bufs[2] = { dyn + C_BUF0, dyn + C_BUF1 };
        int cur = 0, tcount = 0;

        // issue one 64x64 tile (row-major, row stride in floats) into buffer slot
        auto issue_tile = [&](int slot, const float* src, int stride) {
            uint32_t sb = (uint32_t)__cvta_generic_to_shared(bufs[slot]);
            #pragma unroll
            for (int rep = 0; rep < 8; rep++) {
                int ch = tid + rep * 128;          // 0..1023
                int r = ch >> 4, q = ch & 15;
                cp_async16(sb + r * 272 + q * 16, src + r * stride + q * 4);
            }
        };

        // tile sequence: 0=Wk, 1=Wv, then per iteration (11 tiles):
        // Wq, IHr, IHz, IHn, HHr, HHz, HHn, W1a, W1b, W2a, W2b
        auto tile_src = [&](int t, const float*& p, int& st) {
            p = nullptr; st = 64;
            if (t == 0) { p = Wk; return; }
            if (t == 1) { p = Wv; return; }
            if (t >= 35) return;
            int u = (t - 2) % 11;
            switch (u) {
                case 0:  p = Wq; break;
                case 1:  p = W_ih; break;
                case 2:  p = W_ih + 64 * 64; break;
                case 3:  p = W_ih + 128 * 64; break;
                case 4:  p = W_hh; break;
                case 5:  p = W_hh + 64 * 64; break;
                case 6:  p = W_hh + 128 * 64; break;
                case 7:  p = W1; break;
                case 8:  p = W1 + 64 * 64; break;
                case 9:  p = W2;      st = 128; break;
                case 10: p = W2 + 64; st = 128; break;
            }
        };

        auto tile_begin = [&]() { cp_wait<1>(); __syncthreads(); };
        auto tile_end = [&]() {
            __syncthreads();
            const float* p; int st;
            tile_src(tcount + 2, p, st);
            if (p) issue_tile(cur, p, st);
            cp_commit();
            cur ^= 1; tcount++;
        };

        // gemm tile: out[n][c] = bias[boff+c] + sum_j act[n][j] * Wtile[c][j]
        // threads: g = tid>>6 (n-half), c = tid&63; each thread does 5 n's.
        const int g = tid >> 6, c = tid & 63;
        auto gemm = [&](const float* act, int apitch,
                        const float* bias, int boff,
                        float* outp, int opitch, int ooff, bool relu) {
            const float* w = bufs[cur];
            float acc[5];
            float bv_ = __ldg(bias + boff + c);
            #pragma unroll
            for (int k = 0; k < 5; k++) acc[k] = bv_;
            const float4* wr = (const float4*)(w + c * 68);
            const float* ab = act + (g * 5) * apitch;
            #pragma unroll
            for (int j4 = 0; j4 < 16; j4++) {
                float4 wv4 = wr[j4];
                #pragma unroll
                for (int k = 0; k < 5; k++) {
                    float4 a = *(const float4*)(ab + k * apitch + j4 * 4);
                    acc[k] = fmaf(wv4.x, a.x, acc[k]);
                    acc[k] = fmaf(wv4.y, a.y, acc[k]);
                    acc[k] = fmaf(wv4.z, a.z, acc[k]);
                    acc[k] = fmaf(wv4.w, a.w, acc[k]);
                }
            }
            #pragma unroll
            for (int k = 0; k < 5; k++) {
                float r = relu ? fmaxf(acc[k], 0.f) : acc[k];
                outp[(g * 5 + k) * opitch + ooff + c] = r;
            }
        };

        // prologue: issue first two tiles, load cc0
        {
            const float* p; int st;
            tile_src(0, p, st); issue_tile(0, p, st); cp_commit();
            tile_src(1, p, st); issue_tile(1, p, st); cp_commit();
        }
        for (int e = tid; e < 640; e += 128) dyn[C_CC + e] = cc0[e];

        // k, v
        tile_begin(); gemm(dyn + C_CC, 64, bk, 0, dyn + C_K, 64, 0, false); tile_end();
        tile_begin(); gemm(dyn + C_CC, 64, bv, 0, dyn + C_V, 64, 0, false); tile_end();

        for (int it = 0; it < 3; it++) {
            // ---- LN1 on s_cc ----
            if (tid < NC) {
                float s = 0.f, s2 = 0.f;
                #pragma unroll 8
                for (int j = 0; j < D; j++) {
                    float x = dyn[C_CC + tid * 64 + j];
                    s += x; s2 += x * x;
                }
                float m = s * (1.0f / D);
                float var = s2 * (1.0f / D) - m * m;
                dyn[C_MEAN + tid] = m;
                dyn[C_RSTD + tid] = rsqrtf(var + 1e-5f);
            }
            __syncthreads();
            for (int e = tid; e < 640; e += 128) {
                int n = e >> 6, i = e & 63;
                dyn[C_TMP + e] = (dyn[C_CC + e] - dyn[C_MEAN + n]) * dyn[C_RSTD + n]
                                 * __ldg(cc_g + i) + __ldg(cc_b + i);
            }
            // q = LN @ Wq.T + bq
            tile_begin(); gemm(dyn + C_TMP, 64, bq, 0, dyn + C_Q, 64, 0, false); tile_end();

            // attn
            if (tid < NC * NC) {
                int an = tid / NC, am = tid % NC;
                float a = 0.f;
                #pragma unroll 8
                for (int j = 0; j < D; j++)
                    a = fmaf(dyn[C_K + an * 64 + j], dyn[C_Q + am * 64 + j], a);
                dyn[C_ATTN + an * NC + am] = a * 0.125f;
            }
            __syncthreads();
            if (tid < NC) {   // softmax over axis 0 (column m)
                int m = tid;
                float mx = dyn[C_ATTN + m];
                #pragma unroll
                for (int r = 1; r < NC; r++) mx = fmaxf(mx, dyn[C_ATTN + r * NC + m]);
                float e[NC], sum = 0.f;
                #pragma unroll
                for (int r = 0; r < NC; r++) {
                    e[r] = __expf(dyn[C_ATTN + r * NC + m] - mx); sum += e[r];
                }
                float inv = 1.0f / sum;
                #pragma unroll
                for (int r = 0; r < NC; r++) dyn[C_ATTN + r * NC + m] = e[r] * inv + 1e-8f;
            }
            __syncthreads();
            if (tid < NC) {   // row renorm
                float sum = 0.f;
                #pragma unroll
                for (int m = 0; m < NC; m++) sum += dyn[C_ATTN + tid * NC + m];
                float inv = 1.0f / sum;
                #pragma unroll
                for (int m = 0; m < NC; m++) dyn[C_ATTN + tid * NC + m] *= inv;
            }
            __syncthreads();
            // updates = attn @ v  -> s_tmp
            for (int e = tid; e < 640; e += 128) {
                int n = e >> 6, i = e & 63;
                float u = 0.f;
                #pragma unroll
                for (int m = 0; m < NC; m++)
                    u = fmaf(dyn[C_ATTN + n * NC + m], dyn[C_V + m * 64 + i], u);
                dyn[C_TMP + e] = u;
            }

            // GRU: 6 tiles
            tile_begin(); gemm(dyn + C_TMP, 64, b_ih, 0,   dyn + C_GI, 192, 0,   false); tile_end();
            tile_begin(); gemm(dyn + C_TMP, 64, b_ih, 64,  dyn + C_GI, 192, 64,  false); tile_end();
            tile_begin(); gemm(dyn + C_TMP, 64, b_ih, 128, dyn + C_GI, 192, 128, false); tile_end();
            tile_begin(); gemm(dyn + C_CC,  64, b_hh, 0,   dyn + C_GH, 192, 0,   false); tile_end();
            tile_begin(); gemm(dyn + C_CC,  64, b_hh, 64,  dyn + C_GH, 192, 64,  false); tile_end();
            tile_begin(); gemm(dyn + C_CC,  64, b_hh, 128, dyn + C_GH, 192, 128, false); tile_end();

            // GRU elementwise -> s_new
            for (int e = tid; e < 640; e += 128) {
                int n = e >> 6, i = e & 63;
                float gi_r = dyn[C_GI + n * 192 + i],       gh_r = dyn[C_GH + n * 192 + i];
                float gi_z = dyn[C_GI + n * 192 + 64 + i],  gh_z = dyn[C_GH + n * 192 + 64 + i];
                float gi_n = dyn[C_GI + n * 192 + 128 + i], gh_n = dyn[C_GH + n * 192 + 128 + i];
                float r = sigmoidf_(gi_r + gh_r);
                float z = sigmoidf_(gi_z + gh_z);
                float nn = tanhf(gi_n + r * gh_n);
                dyn[C_NEW + e] = (1.0f - z) * nn + z * dyn[C_CC + e];
            }
            __syncthreads();

            // LN2 on s_new
            if (tid < NC) {
                float s = 0.f, s2 = 0.f;
                #pragma unroll 8
                for (int j = 0; j < D; j++) {
                    float x = dyn[C_NEW + tid * 64 + j];
                    s += x; s2 += x * x;
                }
                float m = s * (1.0f / D);
                float var = s2 * (1.0f / D) - m * m;
                dyn[C_MEAN + tid] = m;
                dyn[C_RSTD + tid] = rsqrtf(var + 1e-5f);
            }
            __syncthreads();
            for (int e = tid; e < 640; e += 128) {
                int n = e >> 6, i = e & 63;
                dyn[C_TMP + e] = (dyn[C_NEW + e] - dyn[C_MEAN + n]) * dyn[C_RSTD + n]
                                 * __ldg(ln_g + i) + __ldg(ln_b + i);
            }

            // h2 = relu(LN2 @ W1.T + b1): two column tiles
            tile_begin(); gemm(dyn + C_TMP, 64, b1, 0,  dyn + C_H2, 128, 0,  true); tile_end();
            tile_begin(); gemm(dyn + C_TMP, 64, b1, 64, dyn + C_H2, 128, 64, true); tile_end();

            // out = s_new + h2 @ W2.T + b2: W2a partial to s_q, W2b adds
            tile_begin(); gemm(dyn + C_H2, 128, b2, 0, dyn + C_Q, 64, 0, false); tile_end();
            tile_begin();
            {
                const float* w = bufs[cur];
                float acc[5] = {0.f, 0.f, 0.f, 0.f, 0.f};
                const float4* wr = (const float4*)(w + c * 68);
                const float* ab = dyn + C_H2 + 64 + (g * 5) * 128;
                #pragma unroll
                for (int j4 = 0; j4 < 16; j4++) {
                    float4 wv4 = wr[j4];
                    #pragma unroll
                    for (int k = 0; k < 5; k++) {
                        float4 a = *(const float4*)(ab + k * 128 + j4 * 4);
                        acc[k] = fmaf(wv4.x, a.x, acc[k]);
                        acc[k] = fmaf(wv4.y, a.y, acc[k]);
                        acc[k] = fmaf(wv4.z, a.z, acc[k]);
                        acc[k] = fmaf(wv4.w, a.w, acc[k]);
                    }
                }
                #pragma unroll
                for (int k = 0; k < 5; k++) {
                    int n = g * 5 + k;
                    dyn[C_CC + n * 64 + c] = dyn[C_NEW + n * 64 + c]
                                           + dyn[C_Q + n * 64 + c] + acc[k];
                }
            }
            tile_end();
        }

        // publish cc and raise the flag
        for (int e = tid; e < 640; e += 128) g_cc[e] = dyn[C_CC + e];
        __threadfence();
        __syncthreads();
        if (tid == 0) atomicExch(&g_flag, 1);

    } else {
        // =================== MLP: 2 slots per block ===================
        float* wa  = dyn + M_WA;
        float* wb  = dyn + M_WB;
        float* ccs = dyn + M_CC;
        float* hs  = dyn + M_H;
        const int slot0 = (blockIdx.x - 1) * 2;

        // stream weights first (independent of the core)
        #pragma unroll
        for (int sl = 0; sl < 2; sl++) {
            const char* gbase = (const char*)(Wa + (size_t)(slot0 + sl) * (D * D));
            uint32_t sbase = (uint32_t)__cvta_generic_to_shared(wa + sl * 4352);
            #pragma unroll
            for (int cch = 0; cch < 8; cch++) {
                int ch = tid + cch * 128;
                int row = ch >> 4, q = ch & 15;
                cp_async16(sbase + row * 272 + q * 16, gbase + ch * 16);
            }
        }
        cp_commit();
        #pragma unroll
        for (int sl = 0; sl < 2; sl++) {
            const char* gbase = (const char*)(Wb + (size_t)(slot0 + sl) * (D * D));
            uint32_t sbase = (uint32_t)__cvta_generic_to_shared(wb + sl * 4352);
            #pragma unroll
            for (int cch = 0; cch < 8; cch++) {
                int ch = tid + cch * 128;
                int row = ch >> 4, q = ch & 15;
                cp_async16(sbase + row * 272 + q * 16, gbase + ch * 16);
            }
        }
        cp_commit();

        // wait for the core's cc
        if (tid == 0) {
            while (atomicAdd(&g_flag, 0) == 0) __nanosleep(128);
        }
        __syncthreads();
        __threadfence();
        for (int t = tid; t < NC * D; t += 128) ccs[t] = g_cc[t];

        const int sl = tid >> 6;
        const int i  = tid & 63;
        const int slot = slot0 + sl;
        float acc[NC];

        cp_wait<1>();
        __syncthreads();

        // Stage 1
        {
            const float4* wrow = (const float4*)(wa + sl * 4352 + i * 68);
            float bias = __ldg(ba + slot * D + i);
            #pragma unroll
            for (int n = 0; n < NC; n++) acc[n] = bias;
            #pragma unroll
            for (int j4 = 0; j4 < D / 4; j4++) {
                float4 w = wrow[j4];
                #pragma unroll
                for (int n = 0; n < NC; n++) {
                    float4 cv = *(const float4*)&ccs[n * D + j4 * 4];
                    acc[n] = fmaf(w.x, cv.x, acc[n]);
                    acc[n] = fmaf(w.y, cv.y, acc[n]);
                    acc[n] = fmaf(w.z, cv.z, acc[n]);
                    acc[n] = fmaf(w.w, cv.w, acc[n]);
                }
            }
            #pragma unroll
            for (int n = 0; n < NC; n++)
                hs[sl * 640 + n * D + i] = fmaxf(acc[n], 0.f);
        }

        cp_wait<0>();
        __syncthreads();

        // Stage 2 + max over n
        {
            const float4* wrow = (const float4*)(wb + sl * 4352 + i * 68);
            float bias = __ldg(bb + slot * D + i);
            #pragma unroll
            for (int n = 0; n < NC; n++) acc[n] = bias;
            #pragma unroll
            for (int j4 = 0; j4 < D / 4; j4++) {
                float4 w = wrow[j4];
                #pragma unroll
                for (int n = 0; n < NC; n++) {
                    float4 h = *(const float4*)&hs[sl * 640 + n * D + j4 * 4];
                    acc[n] = fmaf(w.x, h.x, acc[n]);
                    acc[n] = fmaf(w.y, h.y, acc[n]);
                    acc[n] = fmaf(w.z, h.z, acc[n]);
                    acc[n] = fmaf(w.w, h.w, acc[n]);
                }
            }
            float m = acc[0];
            #pragma unroll
            for (int n = 1; n < NC; n++) m = fmaxf(m, acc[n]);
            out[slot * D + i] = m;
        }
    }
}

// ---------------------------------------------------------------------------
extern "C" void kernel_launch(void* const* d_in, const int* in_sizes, int n_in,
                              void* d_out, int out_size)
{
    const float* cc0  = (const float*)d_in[0];
    const float* Wk   = (const float*)d_in[1];
    const float* bk   = (const float*)d_in[2];
    const float* Wq   = (const float*)d_in[3];
    const float* bq   = (const float*)d_in[4];
    const float* Wv   = (const float*)d_in[5];
    const float* bv   = (const float*)d_in[6];
    const float* cc_g = (const float*)d_in[7];
    const float* cc_b = (const float*)d_in[8];
    const float* W_ih = (const float*)d_in[9];
    const float* W_hh = (const float*)d_in[10];
    const float* b_ih = (const float*)d_in[11];
    const float* b_hh = (const float*)d_in[12];
    const float* ln_g = (const float*)d_in[13];
    const float* ln_b = (const float*)d_in[14];
    const float* W1   = (const float*)d_in[15];
    const float* b1   = (const float*)d_in[16];
    const float* W2   = (const float*)d_in[17];
    const float* b2   = (const float*)d_in[18];
    const float* Wa   = (const float*)d_in[19];
    const float* ba   = (const float*)d_in[20];
    const float* Wb   = (const float*)d_in[21];
    const float* bb   = (const float*)d_in[22];

    cudaFuncSetAttribute(fused_kernel,
                         cudaFuncAttributeMaxDynamicSharedMemorySize, DYN_BYTES);

    reset_kernel<<<1, 1>>>();
    fused_kernel<<<1 + 4096 / 2, 128, DYN_BYTES>>>(
        cc0, Wk, bk, Wq, bq, Wv, bv, cc_g, cc_b,
        W_ih, W_hh, b_ih, b_hh, ln_g, ln_b, W1, b1, W2, b2,
        Wa, ba, Wb, bb, (float*)d_out);
}

// round 4
// speedup vs baseline: 1.5591x; 1.5591x over previous
#include <cuda_runtime.h>
#include <cstdint>

#define NC 10
#define D  64

__device__ float g_cc[NC * D];

__device__ __forceinline__ float sigmoidf_(float x) {
    return 1.0f / (1.0f + __expf(-x));
}

__device__ __forceinline__ void cp_async16(uint32_t smem_addr, const void* gptr) {
    asm volatile("cp.async.cg.shared.global [%0], [%1], 16;\n"
                 :: "r"(smem_addr), "l"(gptr));
}
__device__ __forceinline__ void cp_commit() {
    asm volatile("cp.async.commit_group;\n");
}
template <int N>
__device__ __forceinline__ void cp_wait() {
    asm volatile("cp.async.wait_group %0;\n" :: "n"(N));
}

// =========================== CORE KERNEL ====================================
// 640 threads. Weight tiles (64x64) streamed double-buffered via cp.async into
// 68-float-pitch smem rows (conflict-free stores; 4-phase float4 reads).
// GEMM thread layout: c = tid&63 (output col), g = tid>>6 (0..9),
// h = g&1 (j-half), p = g>>1 (n-pair {2p,2p+1}). Each weight byte read 5x
// (vs 10x before); acts broadcast. j-halves combined via smem partials.
//
// smem layout (floats):
#define C_BUF0 0
#define C_BUF1 4352
#define C_CC   8704
#define C_K    9344
#define C_V    9984
#define C_TMP  10624
#define C_Q    11264
#define C_NEW  11904
#define C_GI   12544      // 10 x 192
#define C_GH   14464      // 10 x 192
#define C_H2   16384      // 10 x 128
#define C_ATTN 17664      // 100
#define C_MEAN 17764
#define C_RSTD 17776
#define C_P1   17792      // 20
#define C_P2   17812      // 20
#define C_PA   17832      // 320 partial acc0
#define C_PB   18152      // 320 partial acc1
#define CORE_DYN_BYTES (18480 * 4)

__global__ void __launch_bounds__(640, 1)
slot_iter_kernel(
    const float* __restrict__ cc0,
    const float* __restrict__ Wk, const float* __restrict__ bk,
    const float* __restrict__ Wq, const float* __restrict__ bq,
    const float* __restrict__ Wv, const float* __restrict__ bv,
    const float* __restrict__ cc_g, const float* __restrict__ cc_b,
    const float* __restrict__ W_ih, const float* __restrict__ W_hh,
    const float* __restrict__ b_ih, const float* __restrict__ b_hh,
    const float* __restrict__ ln_g, const float* __restrict__ ln_b,
    const float* __restrict__ W1, const float* __restrict__ b1,
    const float* __restrict__ W2, const float* __restrict__ b2)
{
    extern __shared__ float dyn[];
    const int tid  = threadIdx.x;
    const int warp = tid >> 5, lane = tid & 31;
    const int nn_  = tid >> 6, ii = tid & 63;   // state-op layout
    const int c = tid & 63, g = tid >> 6;       // gemm layout
    const int h = g & 1, p = g >> 1;
    const int n0 = 2 * p, n1 = 2 * p + 1;

    float* bufs[2] = { dyn + C_BUF0, dyn + C_BUF1 };
    int cur = 0, tcount = 0;

    // stream one 64x64 tile, src row-major with row stride st (floats)
    auto issue_tile = [&](int slot, const float* src, int st) {
        uint32_t sb = (uint32_t)__cvta_generic_to_shared(bufs[slot]);
        #pragma unroll
        for (int rep = 0; rep < 2; rep++) {
            int ch = tid + rep * 640;
            if (ch < 1024) {
                int r = ch >> 4, q = ch & 15;
                cp_async16(sb + r * 272 + q * 16,
                           (const char*)src + (size_t)(r * st + q * 4) * 4);
            }
        }
    };

    // tile order: 0=Wk, 1=Wv, then per iter: Wq, IHr,IHz,IHn, HHr,HHz,HHn,
    // W1a, W1b, W2a, W2b
    auto tile_src = [&](int t, const float*& ptr, int& st) {
        ptr = nullptr; st = 64;
        if (t == 0) { ptr = Wk; return; }
        if (t == 1) { ptr = Wv; return; }
        if (t >= 35) return;
        switch ((t - 2) % 11) {
            case 0:  ptr = Wq; break;
            case 1:  ptr = W_ih; break;
            case 2:  ptr = W_ih + 64 * 64; break;
            case 3:  ptr = W_ih + 128 * 64; break;
            case 4:  ptr = W_hh; break;
            case 5:  ptr = W_hh + 64 * 64; break;
            case 6:  ptr = W_hh + 128 * 64; break;
            case 7:  ptr = W1; break;
            case 8:  ptr = W1 + 64 * 64; break;
            case 9:  ptr = W2;      st = 128; break;
            case 10: ptr = W2 + 64; st = 128; break;
        }
    };

    auto tile_begin = [&]() { cp_wait<1>(); __syncthreads(); };
    auto tile_end = [&]() {
        const float* ptr; int st;
        tile_src(tcount + 2, ptr, st);
        if (ptr) issue_tile(cur, ptr, st);
        cp_commit();
        cur ^= 1; tcount++;
    };

    // mode: 0 = bias, 1 = bias+relu, 2 = final (acc + qbuf + neww -> cc)
    auto gemm = [&](const float* act, int apitch,
                    const float* bias, int boff,
                    float* outp, int opitch, int ooff, int mode) {
        const float4* w  = (const float4*)(bufs[cur] + c * 68 + h * 32);
        const float4* a0 = (const float4*)(act + n0 * apitch + h * 32);
        const float4* a1 = (const float4*)(act + n1 * apitch + h * 32);
        float acc0 = 0.f, acc1 = 0.f;
        #pragma unroll
        for (int j4 = 0; j4 < 8; j4++) {
            float4 wv = w[j4];
            float4 x0 = a0[j4];
            float4 x1 = a1[j4];
            acc0 = fmaf(wv.x, x0.x, acc0); acc1 = fmaf(wv.x, x1.x, acc1);
            acc0 = fmaf(wv.y, x0.y, acc0); acc1 = fmaf(wv.y, x1.y, acc1);
            acc0 = fmaf(wv.z, x0.z, acc0); acc1 = fmaf(wv.z, x1.z, acc1);
            acc0 = fmaf(wv.w, x0.w, acc0); acc1 = fmaf(wv.w, x1.w, acc1);
        }
        if (h == 1) {
            dyn[C_PA + p * 64 + c] = acc0;
            dyn[C_PB + p * 64 + c] = acc1;
        }
        __syncthreads();
        if (h == 0) {
            float r0 = acc0 + dyn[C_PA + p * 64 + c];
            float r1 = acc1 + dyn[C_PB + p * 64 + c];
            if (mode == 2) {
                r0 += dyn[C_Q + n0 * 64 + c] + dyn[C_NEW + n0 * 64 + c];
                r1 += dyn[C_Q + n1 * 64 + c] + dyn[C_NEW + n1 * 64 + c];
            } else {
                float b = __ldg(bias + boff + c);
                r0 += b; r1 += b;
                if (mode == 1) { r0 = fmaxf(r0, 0.f); r1 = fmaxf(r1, 0.f); }
            }
            outp[n0 * opitch + ooff + c] = r0;
            outp[n1 * opitch + ooff + c] = r1;
        }
    };

    // warp-shuffle LN over rows (20 warps: warps 2n,2n+1 cover row n)
    auto layernorm = [&](const float* src, const float* gg, const float* bb_,
                         float* dst) {
        float x = src[nn_ * 64 + ii];
        float s = x, s2 = x * x;
        #pragma unroll
        for (int o = 16; o; o >>= 1) {
            s  += __shfl_down_sync(0xffffffffu, s,  o);
            s2 += __shfl_down_sync(0xffffffffu, s2, o);
        }
        if (lane == 0) { dyn[C_P1 + warp] = s; dyn[C_P2 + warp] = s2; }
        __syncthreads();
        if (tid < NC) {
            float ss  = dyn[C_P1 + 2 * tid] + dyn[C_P1 + 2 * tid + 1];
            float ss2 = dyn[C_P2 + 2 * tid] + dyn[C_P2 + 2 * tid + 1];
            float m = ss * (1.0f / D);
            float var = ss2 * (1.0f / D) - m * m;
            dyn[C_MEAN + tid] = m;
            dyn[C_RSTD + tid] = rsqrtf(var + 1e-5f);
        }
        __syncthreads();
        dst[nn_ * 64 + ii] = (src[nn_ * 64 + ii] - dyn[C_MEAN + nn_]) * dyn[C_RSTD + nn_]
                             * __ldg(gg + ii) + __ldg(bb_ + ii);
    };

    // prologue
    {
        const float* ptr; int st;
        tile_src(0, ptr, st); issue_tile(0, ptr, st); cp_commit();
        tile_src(1, ptr, st); issue_tile(1, ptr, st); cp_commit();
    }
    dyn[C_CC + tid] = cc0[tid];

    tile_begin(); gemm(dyn + C_CC, 64, bk, 0, dyn + C_K, 64, 0, 0); tile_end();
    tile_begin(); gemm(dyn + C_CC, 64, bv, 0, dyn + C_V, 64, 0, 0); tile_end();

    for (int it = 0; it < 3; it++) {
        __syncthreads();
        layernorm(dyn + C_CC, cc_g, cc_b, dyn + C_TMP);

        tile_begin(); gemm(dyn + C_TMP, 64, bq, 0, dyn + C_Q, 64, 0, 0); tile_end();
        __syncthreads();   // q visible

        // attn
        if (tid < NC * NC) {
            int an = tid / NC, am = tid % NC;
            float a = 0.f;
            #pragma unroll 8
            for (int j = 0; j < D; j++)
                a = fmaf(dyn[C_K + an * 64 + j], dyn[C_Q + am * 64 + j], a);
            dyn[C_ATTN + an * NC + am] = a * 0.125f;
        }
        __syncthreads();
        if (tid < NC) {   // softmax over axis 0 (column m)
            int m = tid;
            float mx = dyn[C_ATTN + m];
            #pragma unroll
            for (int r = 1; r < NC; r++) mx = fmaxf(mx, dyn[C_ATTN + r * NC + m]);
            float e[NC], sum = 0.f;
            #pragma unroll
            for (int r = 0; r < NC; r++) {
                e[r] = __expf(dyn[C_ATTN + r * NC + m] - mx); sum += e[r];
            }
            float inv = 1.0f / sum;
            #pragma unroll
            for (int r = 0; r < NC; r++) dyn[C_ATTN + r * NC + m] = e[r] * inv + 1e-8f;
        }
        __syncthreads();
        if (tid < NC) {   // row renorm
            float sum = 0.f;
            #pragma unroll
            for (int m = 0; m < NC; m++) sum += dyn[C_ATTN + tid * NC + m];
            float inv = 1.0f / sum;
            #pragma unroll
            for (int m = 0; m < NC; m++) dyn[C_ATTN + tid * NC + m] *= inv;
        }
        __syncthreads();
        // updates = attn @ v
        {
            float u = 0.f;
            #pragma unroll
            for (int m = 0; m < NC; m++)
                u = fmaf(dyn[C_ATTN + nn_ * NC + m], dyn[C_V + m * 64 + ii], u);
            dyn[C_TMP + nn_ * 64 + ii] = u;
        }

        // GRU gates (6 tiles)
        tile_begin(); gemm(dyn + C_TMP, 64, b_ih, 0,   dyn + C_GI, 192, 0,   0); tile_end();
        tile_begin(); gemm(dyn + C_TMP, 64, b_ih, 64,  dyn + C_GI, 192, 64,  0); tile_end();
        tile_begin(); gemm(dyn + C_TMP, 64, b_ih, 128, dyn + C_GI, 192, 128, 0); tile_end();
        tile_begin(); gemm(dyn + C_CC,  64, b_hh, 0,   dyn + C_GH, 192, 0,   0); tile_end();
        tile_begin(); gemm(dyn + C_CC,  64, b_hh, 64,  dyn + C_GH, 192, 64,  0); tile_end();
        tile_begin(); gemm(dyn + C_CC,  64, b_hh, 128, dyn + C_GH, 192, 128, 0); tile_end();
        __syncthreads();  // gi/gh visible

        // GRU elementwise -> s_new
        {
            float gi_r = dyn[C_GI + nn_ * 192 + ii],       gh_r = dyn[C_GH + nn_ * 192 + ii];
            float gi_z = dyn[C_GI + nn_ * 192 + 64 + ii],  gh_z = dyn[C_GH + nn_ * 192 + 64 + ii];
            float gi_n = dyn[C_GI + nn_ * 192 + 128 + ii], gh_n = dyn[C_GH + nn_ * 192 + 128 + ii];
            float r = sigmoidf_(gi_r + gh_r);
            float z = sigmoidf_(gi_z + gh_z);
            float nv = tanhf(gi_n + r * gh_n);
            dyn[C_NEW + nn_ * 64 + ii] = (1.0f - z) * nv + z * dyn[C_CC + nn_ * 64 + ii];
        }
        __syncthreads();

        layernorm(dyn + C_NEW, ln_g, ln_b, dyn + C_TMP);

        // h2 = relu(LN2 @ W1.T + b1)
        tile_begin(); gemm(dyn + C_TMP, 64, b1, 0,  dyn + C_H2, 128, 0,  1); tile_end();
        tile_begin(); gemm(dyn + C_TMP, 64, b1, 64, dyn + C_H2, 128, 64, 1); tile_end();

        // cc = s_new + h2 @ W2.T + b2 (two K-tiles; b2 folded into first)
        tile_begin(); gemm(dyn + C_H2, 128, b2, 0, dyn + C_Q, 64, 0, 0); tile_end();
        tile_begin(); gemm(dyn + C_H2 + 64, 128, b2, 0, dyn + C_CC, 64, 0, 2); tile_end();
    }
    __syncthreads();
    g_cc[tid] = dyn[C_CC + tid];
}

// =========================== MLP KERNEL =====================================
// 1 slot per 128-thread block, dual-buffered Wa/Wb (both issued upfront).
// smem 42.5KB -> 5 blocks/SM. Thread (i = tid&63 output feature,
// h = tid>>6 j-half); partials combined in smem.
// smem: wa 4352 | wb 4352 | cc 640 | hs 640 | part 640  = 10624 floats
#define M_WA   0
#define M_WB   4352
#define M_CC   8704
#define M_HS   9344
#define M_PART 9984
#define MLP_DYN_BYTES (10624 * 4)

__global__ void __launch_bounds__(128, 5)
slot_mlp_kernel(
    const float* __restrict__ Wa, const float* __restrict__ ba,
    const float* __restrict__ Wb, const float* __restrict__ bb,
    float* __restrict__ out)
{
    extern __shared__ float sm[];
    const int tid = threadIdx.x;
    const int slot = blockIdx.x;
    const int i = tid & 63, h = tid >> 6;

    // stream both weight matrices up front
    {
        const char* ga = (const char*)(Wa + (size_t)slot * (D * D));
        uint32_t sa = (uint32_t)__cvta_generic_to_shared(sm + M_WA);
        #pragma unroll
        for (int cch = 0; cch < 8; cch++) {
            int ch = tid + cch * 128;
            int r = ch >> 4, q = ch & 15;
            cp_async16(sa + r * 272 + q * 16, ga + ch * 16);
        }
        cp_commit();
        const char* gb = (const char*)(Wb + (size_t)slot * (D * D));
        uint32_t sb = (uint32_t)__cvta_generic_to_shared(sm + M_WB);
        #pragma unroll
        for (int cch = 0; cch < 8; cch++) {
            int ch = tid + cch * 128;
            int r = ch >> 4, q = ch & 15;
            cp_async16(sb + r * 272 + q * 16, gb + ch * 16);
        }
        cp_commit();
    }

    for (int t = tid; t < NC * D; t += 128)
        sm[M_CC + t] = g_cc[t];

    float acc[NC];

    cp_wait<1>();
    __syncthreads();

    // Stage 1: partial dot over this thread's j-half
    {
        const float4* w = (const float4*)(sm + M_WA + i * 68 + h * 32);
        #pragma unroll
        for (int n = 0; n < NC; n++) acc[n] = 0.f;
        #pragma unroll
        for (int j4 = 0; j4 < 8; j4++) {
            float4 wv = w[j4];
            #pragma unroll
            for (int n = 0; n < NC; n++) {
                float4 x = *(const float4*)&sm[M_CC + n * 64 + h * 32 + j4 * 4];
                acc[n] = fmaf(wv.x, x.x, acc[n]);
                acc[n] = fmaf(wv.y, x.y, acc[n]);
                acc[n] = fmaf(wv.z, x.z, acc[n]);
                acc[n] = fmaf(wv.w, x.w, acc[n]);
            }
        }
        if (h == 1) {
            #pragma unroll
            for (int n = 0; n < NC; n++) sm[M_PART + n * 64 + i] = acc[n];
        }
        __syncthreads();
        if (h == 0) {
            float bias = __ldg(ba + slot * D + i);
            #pragma unroll
            for (int n = 0; n < NC; n++)
                sm[M_HS + n * 64 + i] = fmaxf(acc[n] + sm[M_PART + n * 64 + i] + bias, 0.f);
        }
    }

    cp_wait<0>();
    __syncthreads();   // hs visible + wb ready

    // Stage 2 + max over n
    {
        const float4* w = (const float4*)(sm + M_WB + i * 68 + h * 32);
        #pragma unroll
        for (int n = 0; n < NC; n++) acc[n] = 0.f;
        #pragma unroll
        for (int j4 = 0; j4 < 8; j4++) {
            float4 wv = w[j4];
            #pragma unroll
            for (int n = 0; n < NC; n++) {
                float4 x = *(const float4*)&sm[M_HS + n * 64 + h * 32 + j4 * 4];
                acc[n] = fmaf(wv.x, x.x, acc[n]);
                acc[n] = fmaf(wv.y, x.y, acc[n]);
                acc[n] = fmaf(wv.z, x.z, acc[n]);
                acc[n] = fmaf(wv.w, x.w, acc[n]);
            }
        }
        if (h == 1) {
            #pragma unroll
            for (int n = 0; n < NC; n++) sm[M_PART + n * 64 + i] = acc[n];
        }
        __syncthreads();
        if (h == 0) {
            float bias = __ldg(bb + slot * D + i);
            float m = -3.4e38f;
            #pragma unroll
            for (int n = 0; n < NC; n++)
                m = fmaxf(m, acc[n] + sm[M_PART + n * 64 + i] + bias);
            out[slot * D + i] = m;
        }
    }
}

// ---------------------------------------------------------------------------
extern "C" void kernel_launch(void* const* d_in, const int* in_sizes, int n_in,
                              void* d_out, int out_size)
{
    const float* cc0  = (const float*)d_in[0];
    const float* Wk   = (const float*)d_in[1];
    const float* bk   = (const float*)d_in[2];
    const float* Wq   = (const float*)d_in[3];
    const float* bq   = (const float*)d_in[4];
    const float* Wv   = (const float*)d_in[5];
    const float* bv   = (const float*)d_in[6];
    const float* cc_g = (const float*)d_in[7];
    const float* cc_b = (const float*)d_in[8];
    const float* W_ih = (const float*)d_in[9];
    const float* W_hh = (const float*)d_in[10];
    const float* b_ih = (const float*)d_in[11];
    const float* b_hh = (const float*)d_in[12];
    const float* ln_g = (const float*)d_in[13];
    const float* ln_b = (const float*)d_in[14];
    const float* W1   = (const float*)d_in[15];
    const float* b1   = (const float*)d_in[16];
    const float* W2   = (const float*)d_in[17];
    const float* b2   = (const float*)d_in[18];
    const float* Wa   = (const float*)d_in[19];
    const float* ba   = (const float*)d_in[20];
    const float* Wb   = (const float*)d_in[21];
    const float* bb   = (const float*)d_in[22];

    cudaFuncSetAttribute(slot_iter_kernel,
                         cudaFuncAttributeMaxDynamicSharedMemorySize, CORE_DYN_BYTES);
    cudaFuncSetAttribute(slot_mlp_kernel,
                         cudaFuncAttributeMaxDynamicSharedMemorySize, MLP_DYN_BYTES);

    slot_iter_kernel<<<1, 640, CORE_DYN_BYTES>>>(
        cc0, Wk, bk, Wq, bq, Wv, bv, cc_g, cc_b,
        W_ih, W_hh, b_ih, b_hh, ln_g, ln_b, W1, b1, W2, b2);
    slot_mlp_kernel<<<4096, 128, MLP_DYN_BYTES>>>(Wa, ba, Wb, bb, (float*)d_out);
}

// round 5
// speedup vs baseline: 1.6215x; 1.0401x over previous
#include <cuda_runtime.h>
#include <cstdint>

#define NC 10
#define D  64

__device__ float g_cc[NC * D];

__device__ __forceinline__ float sigmoidf_(float x) {
    return 1.0f / (1.0f + __expf(-x));
}

__device__ __forceinline__ void cp_async16(uint32_t smem_addr, const void* gptr) {
    asm volatile("cp.async.cg.shared.global [%0], [%1], 16;\n"
                 :: "r"(smem_addr), "l"(gptr));
}
__device__ __forceinline__ void cp_commit() {
    asm volatile("cp.async.commit_group;\n");
}
template <int N>
__device__ __forceinline__ void cp_wait() {
    asm volatile("cp.async.wait_group %0;\n" :: "n"(N));
}
__device__ __forceinline__ void l2_prefetch(const void* p) {
    asm volatile("prefetch.global.L2 [%0];" :: "l"(p));
}

// =========================== CORE + PREFETCH KERNEL =========================
// Block 0 (640 thr): slot-attention core, ring-4 double... quad-buffered tile
// streaming, prefetch depth 3 (tiles t+1..t+3 always in flight).
// Blocks 1..147: prefetch.global.L2 over Wa/Wb (134MB) so the MLP kernel
// reads warm L2.
//
// smem layout (floats):
#define C_BUF   0          // 4 x 4352
#define C_CC    17408
#define C_K     18048
#define C_V     18688
#define C_TMP   19328
#define C_Q     19968
#define C_NEW   20608
#define C_GI    21248      // 10 x 192
#define C_GH    23168      // 10 x 192
#define C_H2    25088      // 10 x 128
#define C_ATTN  26368      // 100
#define C_MEAN  26468
#define C_RSTD  26480
#define C_P1    26496      // 20
#define C_P2    26516      // 20
#define C_PA    26536      // 320
#define C_PB    26856      // 320
#define CORE_DYN_BYTES (27200 * 4)

__global__ void __launch_bounds__(640, 1)
slot_iter_kernel(
    const float* __restrict__ cc0,
    const float* __restrict__ Wk, const float* __restrict__ bk,
    const float* __restrict__ Wq, const float* __restrict__ bq,
    const float* __restrict__ Wv, const float* __restrict__ bv,
    const float* __restrict__ cc_g, const float* __restrict__ cc_b,
    const float* __restrict__ W_ih, const float* __restrict__ W_hh,
    const float* __restrict__ b_ih, const float* __restrict__ b_hh,
    const float* __restrict__ ln_g, const float* __restrict__ ln_b,
    const float* __restrict__ W1, const float* __restrict__ b1,
    const float* __restrict__ W2, const float* __restrict__ b2,
    const float* __restrict__ Wa, const float* __restrict__ Wb)
{
    extern __shared__ float dyn[];
    const int tid = threadIdx.x;

    if (blockIdx.x != 0) {
        // ---- L2 prefetch of the MLP weights (consumed by the next kernel) ----
        // 4096 slots x 2 matrices x 16KB = 134MB = 2 x 524288 lines of 128B.
        const int nlines = 4096 * 128;       // per matrix
        const int gt = (blockIdx.x - 1) * 640 + tid;
        const int stride = 147 * 640;
        const char* pa = (const char*)Wa;
        const char* pb = (const char*)Wb;
        for (int idx = gt; idx < nlines; idx += stride) {
            l2_prefetch(pa + (size_t)idx * 128);
            l2_prefetch(pb + (size_t)idx * 128);
        }
        return;
    }

    const int warp = tid >> 5, lane = tid & 31;
    const int nn_  = tid >> 6, ii = tid & 63;   // state-op layout
    const int c = tid & 63, g = tid >> 6;       // gemm layout
    const int h = g & 1, p = g >> 1;
    const int n0 = 2 * p, n1 = 2 * p + 1;

    int tcount = 0;   // index of tile currently being computed

    // stream one 64x64 tile, src row-major with row stride st (floats)
    auto issue_tile = [&](int slot, const float* src, int st) {
        uint32_t sb = (uint32_t)__cvta_generic_to_shared(dyn + C_BUF + slot * 4352);
        #pragma unroll
        for (int rep = 0; rep < 2; rep++) {
            int ch = tid + rep * 640;
            if (ch < 1024) {
                int r = ch >> 4, q = ch & 15;
                cp_async16(sb + r * 272 + q * 16,
                           (const char*)src + (size_t)(r * st + q * 4) * 4);
            }
        }
    };

    // tile order: 0=Wk, 1=Wv, then per iter: Wq, IHr,IHz,IHn, HHr,HHz,HHn,
    // W1a, W1b, W2a, W2b     (35 tiles total)
    auto tile_src = [&](int t, const float*& ptr, int& st) {
        ptr = nullptr; st = 64;
        if (t == 0) { ptr = Wk; return; }
        if (t == 1) { ptr = Wv; return; }
        if (t >= 35) return;
        switch ((t - 2) % 11) {
            case 0:  ptr = Wq; break;
            case 1:  ptr = W_ih; break;
            case 2:  ptr = W_ih + 64 * 64; break;
            case 3:  ptr = W_ih + 128 * 64; break;
            case 4:  ptr = W_hh; break;
            case 5:  ptr = W_hh + 64 * 64; break;
            case 6:  ptr = W_hh + 128 * 64; break;
            case 7:  ptr = W1; break;
            case 8:  ptr = W1 + 64 * 64; break;
            case 9:  ptr = W2;      st = 128; break;
            case 10: ptr = W2 + 64; st = 128; break;
        }
    };

    // tile tcount ready when <=2 newer groups pending (t+1..t+3 in flight)
    auto tile_begin = [&]() { cp_wait<2>(); __syncthreads(); };
    auto tile_end = [&]() {
        const float* ptr; int st;
        tile_src(tcount + 3, ptr, st);
        if (ptr) { issue_tile((tcount + 3) & 3, ptr, st); }
        cp_commit();
        tcount++;
    };

    // mode: 0 = bias, 1 = bias+relu, 2 = final (acc + qbuf + neww -> cc)
    auto gemm = [&](const float* act, int apitch,
                    const float* bias, int boff,
                    float* outp, int opitch, int ooff, int mode) {
        const float4* w  = (const float4*)(dyn + C_BUF + (tcount & 3) * 4352
                                           + c * 68 + h * 32);
        const float4* a0 = (const float4*)(act + n0 * apitch + h * 32);
        const float4* a1 = (const float4*)(act + n1 * apitch + h * 32);
        float acc0 = 0.f, acc1 = 0.f;
        #pragma unroll
        for (int j4 = 0; j4 < 8; j4++) {
            float4 wv = w[j4];
            float4 x0 = a0[j4];
            float4 x1 = a1[j4];
            acc0 = fmaf(wv.x, x0.x, acc0); acc1 = fmaf(wv.x, x1.x, acc1);
            acc0 = fmaf(wv.y, x0.y, acc0); acc1 = fmaf(wv.y, x1.y, acc1);
            acc0 = fmaf(wv.z, x0.z, acc0); acc1 = fmaf(wv.z, x1.z, acc1);
            acc0 = fmaf(wv.w, x0.w, acc0); acc1 = fmaf(wv.w, x1.w, acc1);
        }
        if (h == 1) {
            dyn[C_PA + p * 64 + c] = acc0;
            dyn[C_PB + p * 64 + c] = acc1;
        }
        __syncthreads();
        if (h == 0) {
            float r0 = acc0 + dyn[C_PA + p * 64 + c];
            float r1 = acc1 + dyn[C_PB + p * 64 + c];
            if (mode == 2) {
                r0 += dyn[C_Q + n0 * 64 + c] + dyn[C_NEW + n0 * 64 + c];
                r1 += dyn[C_Q + n1 * 64 + c] + dyn[C_NEW + n1 * 64 + c];
            } else {
                float b = __ldg(bias + boff + c);
                r0 += b; r1 += b;
                if (mode == 1) { r0 = fmaxf(r0, 0.f); r1 = fmaxf(r1, 0.f); }
            }
            outp[n0 * opitch + ooff + c] = r0;
            outp[n1 * opitch + ooff + c] = r1;
        }
    };

    auto layernorm = [&](const float* src, const float* gg, const float* bb_,
                         float* dst) {
        float x = src[nn_ * 64 + ii];
        float s = x, s2 = x * x;
        #pragma unroll
        for (int o = 16; o; o >>= 1) {
            s  += __shfl_down_sync(0xffffffffu, s,  o);
            s2 += __shfl_down_sync(0xffffffffu, s2, o);
        }
        if (lane == 0) { dyn[C_P1 + warp] = s; dyn[C_P2 + warp] = s2; }
        __syncthreads();
        if (tid < NC) {
            float ss  = dyn[C_P1 + 2 * tid] + dyn[C_P1 + 2 * tid + 1];
            float ss2 = dyn[C_P2 + 2 * tid] + dyn[C_P2 + 2 * tid + 1];
            float m = ss * (1.0f / D);
            float var = ss2 * (1.0f / D) - m * m;
            dyn[C_MEAN + tid] = m;
            dyn[C_RSTD + tid] = rsqrtf(var + 1e-5f);
        }
        __syncthreads();
        dst[nn_ * 64 + ii] = (src[nn_ * 64 + ii] - dyn[C_MEAN + nn_]) * dyn[C_RSTD + nn_]
                             * __ldg(gg + ii) + __ldg(bb_ + ii);
    };

    // prologue: issue tiles 0..2
    {
        const float* ptr; int st;
        tile_src(0, ptr, st); issue_tile(0, ptr, st); cp_commit();
        tile_src(1, ptr, st); issue_tile(1, ptr, st); cp_commit();
        tile_src(2, ptr, st); issue_tile(2, ptr, st); cp_commit();
    }
    dyn[C_CC + tid] = cc0[tid];

    tile_begin(); gemm(dyn + C_CC, 64, bk, 0, dyn + C_K, 64, 0, 0); tile_end();
    tile_begin(); gemm(dyn + C_CC, 64, bv, 0, dyn + C_V, 64, 0, 0); tile_end();

    for (int it = 0; it < 3; it++) {
        __syncthreads();
        layernorm(dyn + C_CC, cc_g, cc_b, dyn + C_TMP);

        tile_begin(); gemm(dyn + C_TMP, 64, bq, 0, dyn + C_Q, 64, 0, 0); tile_end();
        __syncthreads();   // q visible

        if (tid < NC * NC) {
            int an = tid / NC, am = tid % NC;
            float a = 0.f;
            #pragma unroll 8
            for (int j = 0; j < D; j++)
                a = fmaf(dyn[C_K + an * 64 + j], dyn[C_Q + am * 64 + j], a);
            dyn[C_ATTN + an * NC + am] = a * 0.125f;
        }
        __syncthreads();
        if (tid < NC) {   // softmax over axis 0 (column m)
            int m = tid;
            float mx = dyn[C_ATTN + m];
            #pragma unroll
            for (int r = 1; r < NC; r++) mx = fmaxf(mx, dyn[C_ATTN + r * NC + m]);
            float e[NC], sum = 0.f;
            #pragma unroll
            for (int r = 0; r < NC; r++) {
                e[r] = __expf(dyn[C_ATTN + r * NC + m] - mx); sum += e[r];
            }
            float inv = 1.0f / sum;
            #pragma unroll
            for (int r = 0; r < NC; r++) dyn[C_ATTN + r * NC + m] = e[r] * inv + 1e-8f;
        }
        __syncthreads();
        if (tid < NC) {   // row renorm
            float sum = 0.f;
            #pragma unroll
            for (int m = 0; m < NC; m++) sum += dyn[C_ATTN + tid * NC + m];
            float inv = 1.0f / sum;
            #pragma unroll
            for (int m = 0; m < NC; m++) dyn[C_ATTN + tid * NC + m] *= inv;
        }
        __syncthreads();
        {   // updates = attn @ v
            float u = 0.f;
            #pragma unroll
            for (int m = 0; m < NC; m++)
                u = fmaf(dyn[C_ATTN + nn_ * NC + m], dyn[C_V + m * 64 + ii], u);
            dyn[C_TMP + nn_ * 64 + ii] = u;
        }

        tile_begin(); gemm(dyn + C_TMP, 64, b_ih, 0,   dyn + C_GI, 192, 0,   0); tile_end();
        tile_begin(); gemm(dyn + C_TMP, 64, b_ih, 64,  dyn + C_GI, 192, 64,  0); tile_end();
        tile_begin(); gemm(dyn + C_TMP, 64, b_ih, 128, dyn + C_GI, 192, 128, 0); tile_end();
        tile_begin(); gemm(dyn + C_CC,  64, b_hh, 0,   dyn + C_GH, 192, 0,   0); tile_end();
        tile_begin(); gemm(dyn + C_CC,  64, b_hh, 64,  dyn + C_GH, 192, 64,  0); tile_end();
        tile_begin(); gemm(dyn + C_CC,  64, b_hh, 128, dyn + C_GH, 192, 128, 0); tile_end();
        __syncthreads();

        {   // GRU elementwise -> s_new
            float gi_r = dyn[C_GI + nn_ * 192 + ii],       gh_r = dyn[C_GH + nn_ * 192 + ii];
            float gi_z = dyn[C_GI + nn_ * 192 + 64 + ii],  gh_z = dyn[C_GH + nn_ * 192 + 64 + ii];
            float gi_n = dyn[C_GI + nn_ * 192 + 128 + ii], gh_n = dyn[C_GH + nn_ * 192 + 128 + ii];
            float r = sigmoidf_(gi_r + gh_r);
            float z = sigmoidf_(gi_z + gh_z);
            float nv = tanhf(gi_n + r * gh_n);
            dyn[C_NEW + nn_ * 64 + ii] = (1.0f - z) * nv + z * dyn[C_CC + nn_ * 64 + ii];
        }
        __syncthreads();

        layernorm(dyn + C_NEW, ln_g, ln_b, dyn + C_TMP);

        tile_begin(); gemm(dyn + C_TMP, 64, b1, 0,  dyn + C_H2, 128, 0,  1); tile_end();
        tile_begin(); gemm(dyn + C_TMP, 64, b1, 64, dyn + C_H2, 128, 64, 1); tile_end();

        tile_begin(); gemm(dyn + C_H2, 128, b2, 0, dyn + C_Q, 64, 0, 0); tile_end();
        tile_begin(); gemm(dyn + C_H2 + 64, 128, b2, 0, dyn + C_CC, 64, 0, 2); tile_end();
    }
    __syncthreads();
    g_cc[tid] = dyn[C_CC + tid];
}

// =========================== MLP KERNEL =====================================
// 1 slot per 128-thread block, Wa/Wb cp.async'd upfront (reads should now hit
// warm L2 thanks to the prefetch blocks in the previous kernel).
#define M_WA   0
#define M_WB   4352
#define M_CC   8704
#define M_HS   9344
#define M_PART 9984
#define MLP_DYN_BYTES (10624 * 4)

__global__ void __launch_bounds__(128, 5)
slot_mlp_kernel(
    const float* __restrict__ Wa, const float* __restrict__ ba,
    const float* __restrict__ Wb, const float* __restrict__ bb,
    float* __restrict__ out)
{
    extern __shared__ float sm[];
    const int tid = threadIdx.x;
    const int slot = blockIdx.x;
    const int i = tid & 63, h = tid >> 6;

    {
        const char* ga = (const char*)(Wa + (size_t)slot * (D * D));
        uint32_t sa = (uint32_t)__cvta_generic_to_shared(sm + M_WA);
        #pragma unroll
        for (int cch = 0; cch < 8; cch++) {
            int ch = tid + cch * 128;
            int r = ch >> 4, q = ch & 15;
            cp_async16(sa + r * 272 + q * 16, ga + ch * 16);
        }
        cp_commit();
        const char* gb = (const char*)(Wb + (size_t)slot * (D * D));
        uint32_t sb = (uint32_t)__cvta_generic_to_shared(sm + M_WB);
        #pragma unroll
        for (int cch = 0; cch < 8; cch++) {
            int ch = tid + cch * 128;
            int r = ch >> 4, q = ch & 15;
            cp_async16(sb + r * 272 + q * 16, gb + ch * 16);
        }
        cp_commit();
    }

    for (int t = tid; t < NC * D; t += 128)
        sm[M_CC + t] = g_cc[t];

    float acc[NC];

    cp_wait<1>();
    __syncthreads();

    // Stage 1
    {
        const float4* w = (const float4*)(sm + M_WA + i * 68 + h * 32);
        #pragma unroll
        for (int n = 0; n < NC; n++) acc[n] = 0.f;
        #pragma unroll
        for (int j4 = 0; j4 < 8; j4++) {
            float4 wv = w[j4];
            #pragma unroll
            for (int n = 0; n < NC; n++) {
                float4 x = *(const float4*)&sm[M_CC + n * 64 + h * 32 + j4 * 4];
                acc[n] = fmaf(wv.x, x.x, acc[n]);
                acc[n] = fmaf(wv.y, x.y, acc[n]);
                acc[n] = fmaf(wv.z, x.z, acc[n]);
                acc[n] = fmaf(wv.w, x.w, acc[n]);
            }
        }
        if (h == 1) {
            #pragma unroll
            for (int n = 0; n < NC; n++) sm[M_PART + n * 64 + i] = acc[n];
        }
        __syncthreads();
        if (h == 0) {
            float bias = __ldg(ba + slot * D + i);
            #pragma unroll
            for (int n = 0; n < NC; n++)
                sm[M_HS + n * 64 + i] = fmaxf(acc[n] + sm[M_PART + n * 64 + i] + bias, 0.f);
        }
    }

    cp_wait<0>();
    __syncthreads();

    // Stage 2 + max over n
    {
        const float4* w = (const float4*)(sm + M_WB + i * 68 + h * 32);
        #pragma unroll
        for (int n = 0; n < NC; n++) acc[n] = 0.f;
        #pragma unroll
        for (int j4 = 0; j4 < 8; j4++) {
            float4 wv = w[j4];
            #pragma unroll
            for (int n = 0; n < NC; n++) {
                float4 x = *(const float4*)&sm[M_HS + n * 64 + h * 32 + j4 * 4];
                acc[n] = fmaf(wv.x, x.x, acc[n]);
                acc[n] = fmaf(wv.y, x.y, acc[n]);
                acc[n] = fmaf(wv.z, x.z, acc[n]);
                acc[n] = fmaf(wv.w, x.w, acc[n]);
            }
        }
        if (h == 1) {
            #pragma unroll
            for (int n = 0; n < NC; n++) sm[M_PART + n * 64 + i] = acc[n];
        }
        __syncthreads();
        if (h == 0) {
            float bias = __ldg(bb + slot * D + i);
            float m = -3.4e38f;
            #pragma unroll
            for (int n = 0; n < NC; n++)
                m = fmaxf(m, acc[n] + sm[M_PART + n * 64 + i] + bias);
            out[slot * D + i] = m;
        }
    }
}

// ---------------------------------------------------------------------------
extern "C" void kernel_launch(void* const* d_in, const int* in_sizes, int n_in,
                              void* d_out, int out_size)
{
    const float* cc0  = (const float*)d_in[0];
    const float* Wk   = (const float*)d_in[1];
    const float* bk   = (const float*)d_in[2];
    const float* Wq   = (const float*)d_in[3];
    const float* bq   = (const float*)d_in[4];
    const float* Wv   = (const float*)d_in[5];
    const float* bv   = (const float*)d_in[6];
    const float* cc_g = (const float*)d_in[7];
    const float* cc_b = (const float*)d_in[8];
    const float* W_ih = (const float*)d_in[9];
    const float* W_hh = (const float*)d_in[10];
    const float* b_ih = (const float*)d_in[11];
    const float* b_hh = (const float*)d_in[12];
    const float* ln_g = (const float*)d_in[13];
    const float* ln_b = (const float*)d_in[14];
    const float* W1   = (const float*)d_in[15];
    const float* b1   = (const float*)d_in[16];
    const float* W2   = (const float*)d_in[17];
    const float* b2   = (const float*)d_in[18];
    const float* Wa   = (const float*)d_in[19];
    const float* ba   = (const float*)d_in[20];
    const float* Wb   = (const float*)d_in[21];
    const float* bb   = (const float*)d_in[22];

    cudaFuncSetAttribute(slot_iter_kernel,
                         cudaFuncAttributeMaxDynamicSharedMemorySize, CORE_DYN_BYTES);
    cudaFuncSetAttribute(slot_mlp_kernel,
                         cudaFuncAttributeMaxDynamicSharedMemorySize, MLP_DYN_BYTES);

    slot_iter_kernel<<<148, 640, CORE_DYN_BYTES>>>(
        cc0, Wk, bk, Wq, bq, Wv, bv, cc_g, cc_b,
        W_ih, W_hh, b_ih, b_hh, ln_g, ln_b, W1, b1, W2, b2, Wa, Wb);
    slot_mlp_kernel<<<4096, 128, MLP_DYN_BYTES>>>(Wa, ba, Wb, bb, (float*)d_out);
}